// round 16
// baseline (speedup 1.0000x reference)
#include <cuda_runtime.h>
#include <math.h>
#include <stdint.h>

// ---------------- constants ----------------
#define NCc 128
#define NTc 256
#define RSTR 264          // refine padded row stride (4 col guards each side)
#define RCHN 35904        // 136*264 floats per refine channel (4 row guards each side)

__device__ __constant__ int c_DILS[15] = {1,2,3,4,6,8,10,12,14,16,18,20,24,28,32};

// ---------------- scratch ----------------
// X/SKIP: [2 pad rows][H rows][2 pad rows] x 16ch x XS. max (256+4)*16*160=665600, (128+4)*16*288=608256
__device__ float g_X[672000];
__device__ float g_SKIP[672000];
// G: (H+4) x 8 x GS. max (260)*8*136=282880, (132)*8*264=278784
__device__ float g_G[290816];
__device__ float g_R2[524288];    // [f(16)][m(128)][t(256)]
__device__ float g_HINP[524288];  // [c(128)][f(16)][t(256)]
__device__ float g_HFT[1048576];  // [g(32)][c(128)][u(256)]
__device__ float g_RA[2297856];   // refine ping [ch(64)][row(136)][RSTR]
__device__ float g_RB[2297856];   // refine pong
__device__ unsigned g_FN;
__device__ unsigned g_barcnt;

__device__ __forceinline__ float dfh_tanh(float x){ return tanhf(x)*0.98f + 0.02f*x; }
__device__ __forceinline__ float dfh_sig (float x){ return 0.98f/(1.0f+expf(-x)) + 0.02f*x; }

// ---------------- packed f32x2 helpers ----------------
__device__ __forceinline__ void fma2(uint64_t &d, uint64_t a, uint64_t b){
    asm("fma.rn.f32x2 %0, %1, %2, %0;" : "+l"(d) : "l"(a), "l"(b));
}
__device__ __forceinline__ uint64_t pack2(float x){
    uint64_t r; asm("mov.b64 %0, {%1, %1};" : "=l"(r) : "f"(x)); return r;
}
__device__ __forceinline__ float2 unpack2(uint64_t v){
    float2 f; asm("mov.b64 {%0, %1}, %2;" : "=f"(f.x), "=f"(f.y) : "l"(v)); return f;
}

// ---------------- cp.async helpers ----------------
__device__ __forceinline__ uint32_t smem_u32(const void* p){
    uint32_t a;
    asm("{ .reg .u64 t; cvta.to.shared.u64 t, %1; cvt.u32.u64 %0, t; }" : "=r"(a) : "l"(p));
    return a;
}
__device__ __forceinline__ void cpasync16(uint32_t dst, const void* src){
    asm volatile("cp.async.cg.shared.global [%0], [%1], 16;" :: "r"(dst), "l"(src));
}
#define CP_COMMIT() asm volatile("cp.async.commit_group;")
#define CP_WAIT0()  asm volatile("cp.async.wait_group 0;")

// ---------------- grid barrier ----------------
__device__ __forceinline__ void gridbar(unsigned &target)
{
    __syncthreads();
    target += gridDim.x;
    if (threadIdx.x == 0) {
        __threadfence();
        atomicAdd(&g_barcnt, 1u);
        while (*((volatile unsigned*)&g_barcnt) < target) { }
        __threadfence();
    }
    __syncthreads();
}

// ---------------- zero helpers ----------------
__global__ void k_zero3()
{
    if (blockIdx.x == 0 && threadIdx.x == 0) g_barcnt = 0u;
    int stride = gridDim.x*blockDim.x;
    for (int i = blockIdx.x*blockDim.x + threadIdx.x; i < 672000; i += stride) {
        g_X[i] = 0.0f; g_SKIP[i] = 0.0f;
        if (i < 290816) g_G[i] = 0.0f;
    }
}
__global__ void k_zeroref()
{
    int stride = gridDim.x*blockDim.x;
    for (int i = blockIdx.x*blockDim.x + threadIdx.x; i < 2297856; i += stride) {
        g_RA[i] = 0.0f; g_RB[i] = 0.0f;
    }
}

// ---------------- input dense (4->16); phase1 row offset = 2*16*160 = 5120 ----------------
__global__ void k_dense1(const float* __restrict__ inc, const float* __restrict__ icc,
                         const float* __restrict__ times, const float* __restrict__ tin,
                         const float* __restrict__ cw, const float* __restrict__ cb)
{
    int t = blockIdx.x, c = threadIdx.x;  // 256 x 128
    float i0 = inc[c*NTc + t];
    float i1 = icc[c*NTc + t];
    float i2 = times[t];
    float i3 = tin[c];
    #pragma unroll
    for (int o = 0; o < 16; ++o) {
        float v = i0*cw[o] + i1*cw[16+o] + i2*cw[32+o] + i3*cw[48+o] + cb[o];
        g_X[5120 + (t*16+o)*160 + c] = dfh_tanh(v);
    }
}

// ---------------- PERSISTENT wave stack: vertical pads, branch-free kh ----------------
template<int H, int W, int XS, int GS>
__global__ __launch_bounds__(256,1) void k_wave_all(
    const float* __restrict__ wy1a, const float* __restrict__ by1a,
    const float* __restrict__ wy2a, const float* __restrict__ by2a,
    const float* __restrict__ wza,  const float* __restrict__ bza)
{
    constexpr int CHUNKS = W >> 5;
    constexpr int RPB    = 8 / CHUNKS;
    constexpr int XOFF   = 2*16*XS;       // row-0 offset in g_X/g_SKIP
    constexpr int GOFF   = 2*8*GS;        // row-0 offset in g_G
    extern __shared__ float4 sDyn[];
    float4* sC = sDyn;            // conv12 buffer (2560 float4)
    float4* sZ = sDyn + 2560;     // convz buffer (1280 float4)
    uint32_t sCa = smem_u32(sC);
    uint32_t sZa = smem_u32(sZ);
    int tidx = threadIdx.x;
    int lane = tidx & 31, warp = tidx >> 5;
    int r = warp / CHUNKS, q = warp - r*CHUNKS;
    int w = (q << 5) + lane;
    int h = blockIdx.x * RPB + r;
    unsigned target = 0;

    // preload layer-0 conv12 weights
    {
        const float4* s1 = (const float4*)wy1a;
        const float4* s2 = (const float4*)wy2a;
        for (int i = tidx; i < 1280; i += 256) {
            cpasync16(sCa + i*16, s1 + i);
            cpasync16(sCa + (1280+i)*16, s2 + i);
        }
        CP_COMMIT(); CP_WAIT0();
    }
    __syncthreads();

    for (int layer = 0; layer < 45; ++layer) {
        int dil = c_DILS[layer % 15];

        // prefetch this layer's convz weights into sZ
        {
            const float4* sz = (const float4*)(wza + layer*5120);
            for (int i = tidx; i < 1280; i += 256)
                cpasync16(sZa + i*16, sz + i);
            CP_COMMIT();
        }

        // ======== phase 1: gated conv pair (16ch -> 8+8 outs), no kh guard ========
        {
            const float* b1 = by1a + layer*8;
            const float* b2 = by2a + layer*8;

            uint64_t a1[4] = {0,0,0,0};
            uint64_t a2[4] = {0,0,0,0};

            #pragma unroll
            for (int kh = 0; kh < 5; ++kh) {
                const float* xrow = g_X + XOFF + (h + kh - 2)*16*XS;   // pad rows are zero
                for (int kw = 0; kw < 8; ++kw) {
                    int cb0 = (q << 5) + kw*dil;
                    if (cb0 >= W) break;               // warp-uniform
                    const float* xp = xrow + cb0 + lane;
                    const ulonglong2* wp1 = (const ulonglong2*)(sC + (kh*8+kw)*32);
                    const ulonglong2* wp2 = (const ulonglong2*)(sC + 1280 + (kh*8+kw)*32);
                    float xs[16];
                    #pragma unroll
                    for (int ci = 0; ci < 16; ++ci) xs[ci] = xp[ci*XS];
                    #pragma unroll
                    for (int ci = 0; ci < 16; ++ci) {
                        uint64_t xv = pack2(xs[ci]);
                        ulonglong2 wA = wp1[2*ci], wB = wp1[2*ci+1];
                        ulonglong2 wC = wp2[2*ci], wD = wp2[2*ci+1];
                        fma2(a1[0], xv, wA.x); fma2(a1[1], xv, wA.y);
                        fma2(a1[2], xv, wB.x); fma2(a1[3], xv, wB.y);
                        fma2(a2[0], xv, wC.x); fma2(a2[1], xv, wC.y);
                        fma2(a2[2], xv, wD.x); fma2(a2[3], xv, wD.y);
                    }
                }
            }
            #pragma unroll
            for (int p = 0; p < 4; ++p) {
                float2 v1 = unpack2(a1[p]);
                float2 v2 = unpack2(a2[p]);
                int o0 = 2*p;
                float g0 = dfh_tanh(v1.x + __ldg(b1+o0))   * dfh_sig(v2.x + __ldg(b2+o0));
                float g1 = dfh_tanh(v1.y + __ldg(b1+o0+1)) * dfh_sig(v2.y + __ldg(b2+o0+1));
                g_G[GOFF + (h*8+o0)*GS + w]   = g0;
                g_G[GOFF + (h*8+o0+1)*GS + w] = g1;
            }
        }
        gridbar(target);
        CP_WAIT0();
        __syncthreads();

        // prefetch NEXT layer's conv12 weights into sC
        if (layer + 1 < 45) {
            const float4* s1 = (const float4*)(wy1a + (layer+1)*5120);
            const float4* s2 = (const float4*)(wy2a + (layer+1)*5120);
            for (int i = tidx; i < 1280; i += 256) {
                cpasync16(sCa + i*16, s1 + i);
                cpasync16(sCa + (1280+i)*16, s2 + i);
            }
            CP_COMMIT();
        }

        // ======== phase 2: z conv (8ch -> all 16 outs), fully branch-free ========
        {
            const float* bz = bza + layer*16;
            uint64_t az[8] = {0,0,0,0,0,0,0,0};

            #pragma unroll
            for (int kh = 0; kh < 5; ++kh) {
                const float* grow = g_G + GOFF + (h + kh - 2)*8*GS + w;   // pad rows zero
                #pragma unroll
                for (int kw = 0; kw < 8; ++kw) {
                    const float* xp = grow + kw;
                    const ulonglong2* wp = (const ulonglong2*)(sZ + (kh*8+kw)*32);
                    float xs[8];
                    #pragma unroll
                    for (int ci = 0; ci < 8; ++ci) xs[ci] = xp[ci*GS];
                    #pragma unroll
                    for (int ci = 0; ci < 8; ++ci) {
                        uint64_t xv = pack2(xs[ci]);
                        ulonglong2 wA = wp[4*ci],   wB = wp[4*ci+1];
                        ulonglong2 wC = wp[4*ci+2], wD = wp[4*ci+3];
                        fma2(az[0], xv, wA.x); fma2(az[1], xv, wA.y);
                        fma2(az[2], xv, wB.x); fma2(az[3], xv, wB.y);
                        fma2(az[4], xv, wC.x); fma2(az[5], xv, wC.y);
                        fma2(az[6], xv, wD.x); fma2(az[7], xv, wD.y);
                    }
                }
            }
            #pragma unroll
            for (int p = 0; p < 8; ++p) {
                float2 v = unpack2(az[p]);
                int oo = 2*p;
                float z0 = v.x + __ldg(bz+oo);
                float z1 = v.y + __ldg(bz+oo+1);
                int idx0 = XOFF + (h*16+oo)*XS + w;
                int idx1 = idx0 + XS;
                g_SKIP[idx0] += z0;  g_X[idx0] += z0;
                g_SKIP[idx1] += z1;  g_X[idx1] += z1;
            }
        }
        gridbar(target);
        CP_WAIT0();
        __syncthreads();
    }
}

// ---------------- stage C1 (SKIP phase-1 offset 5120) ----------------
__global__ void k_c1()
{
    int t = blockIdx.x, f = blockIdx.y;     // 256 x 16
    __shared__ float vr[64], vi[64], tc[128], ts[128];
    int tid = threadIdx.x;                  // 128
    if (tid < 64) {
        int k = tid;
        float cr = g_SKIP[5120 + (t*16+f)*160 + 2*k];
        float ci = g_SKIP[5120 + (t*16+f)*160 + 2*k+1];
        cr = dfh_tanh(cr); ci = dfh_tanh(ci);
        float s = ((k==0)?0.5f:1.0f) * ((k&1)?-1.0f:1.0f);
        vr[k] = s*cr; vi[k] = s*ci;
    }
    {
        float sv, cv; sincospif((float)tid * (1.0f/64.0f), &sv, &cv);
        tc[tid] = cv; ts[tid] = sv;
    }
    __syncthreads();
    int m = tid;
    float acc = 0.0f;
    #pragma unroll 8
    for (int k = 0; k < 64; ++k) {
        int j = (k*m) & 127;
        acc += vr[k]*tc[j] + vi[k]*ts[j];
    }
    g_R2[(f*128+m)*NTc + t] = acc;
}

// ---------------- stage C2 ----------------
__global__ void k_c2(const float* __restrict__ times)
{
    int m = blockIdx.x, f = blockIdx.y;     // 128 x 16
    __shared__ float v[256], tc[256], ts[256];
    int tid = threadIdx.x;                  // 128
    v[tid]       = g_R2[(f*128+m)*NTc + tid];
    v[tid+128]   = g_R2[(f*128+m)*NTc + tid + 128];
    {
        float sv, cv;
        sincospif((float)tid * (1.0f/128.0f), &sv, &cv);        tc[tid] = cv;      ts[tid] = sv;
        sincospif((float)(tid+128) * (1.0f/128.0f), &sv, &cv);  tc[tid+128] = cv;  ts[tid+128] = sv;
    }
    __syncthreads();
    int k = tid;
    float zm = (k==0) ? 1.0f : ((fabsf(times[2*k]) > 0.0f) ? 1.0f : 0.0f);
    float scale = zm * ((k&1)?-1.0f:1.0f) * (1.0f/128.0f);
    float ar = 0.0f, ai = 0.0f;
    #pragma unroll 8
    for (int t = 0; t < 256; ++t) {
        int j = (t*k) & 255;
        ar += v[t]*tc[j];
        ai += v[t]*ts[j];
    }
    g_HINP[(m*16+f)*NTc + 2*k]   = scale*ar;
    g_HINP[(m*16+f)*NTc + 2*k+1] = scale*ai;
}

// ---------------- dense2 (16->16); phase2 row offset = 2*16*288 = 9216 ----------------
__global__ void k_dense2(const float* __restrict__ hw, const float* __restrict__ hb)
{
    int c = blockIdx.x;       // 128
    int t = threadIdx.x;      // 256
    float in[16];
    #pragma unroll
    for (int f = 0; f < 16; ++f) in[f] = g_HINP[(c*16+f)*NTc + t];
    #pragma unroll
    for (int o = 0; o < 16; ++o) {
        float acc = hb[o];
        #pragma unroll
        for (int f = 0; f < 16; ++f) acc += in[f]*hw[f*16+o];
        g_X[9216 + (c*16+o)*288 + t] = dfh_tanh(acc);
    }
}

// ---------------- stage D (SKIP phase-2 offset 9216) ----------------
__global__ void k_stageD()
{
    int c = blockIdx.x, g = blockIdx.y;     // 128 x 32
    __shared__ float hr[128], hi[128], tc[256], ts[256];
    int tid = threadIdx.x;                  // 256
    if (tid < 128) {
        int j = tid;
        float v0, v1;
        if (g < 16) {
            float a = g_SKIP[9216 + (c*16+g)*288 + 2*j];   v0 = dfh_tanh(a);
            float b = g_SKIP[9216 + (c*16+g)*288 + 2*j+1]; v1 = dfh_tanh(b);
        } else {
            v0 = g_HINP[(c*16+(g-16))*NTc + 2*j];
            v1 = g_HINP[(c*16+(g-16))*NTc + 2*j+1];
        }
        float s = ((j==0)?0.5f:1.0f) * ((j&1)?-1.0f:1.0f);
        hr[j] = s*v0; hi[j] = s*v1;
    }
    {
        float sv, cv; sincospif((float)tid * (1.0f/128.0f), &sv, &cv);
        tc[tid] = cv; ts[tid] = sv;
    }
    __syncthreads();
    int u = tid;
    float acc = 0.0f;
    #pragma unroll 8
    for (int j = 0; j < 128; ++j) {
        int idx = (j*u) & 255;
        acc += hr[j]*tc[idx] + hi[j]*ts[idx];
    }
    g_HFT[(g*128+c)*NTc + u] = acc;
}

// ---------------- fnorm ----------------
__global__ void k_fninit(){ g_FN = 0u; }

__global__ void k_fnred()
{
    int stride = gridDim.x*blockDim.x;
    float mx = 0.0f;
    for (int i = blockIdx.x*blockDim.x + threadIdx.x; i < 1048576; i += stride)
        mx = fmaxf(mx, fabsf(g_HFT[i]));
    #pragma unroll
    for (int o = 16; o; o >>= 1) mx = fmaxf(mx, __shfl_xor_sync(0xFFFFFFFFu, mx, o));
    __shared__ float sm[8];
    int lane = threadIdx.x & 31, warp = threadIdx.x >> 5;
    if (lane == 0) sm[warp] = mx;
    __syncthreads();
    if (warp == 0) {
        mx = (lane < 8) ? sm[lane] : 0.0f;
        #pragma unroll
        for (int o = 4; o; o >>= 1) mx = fmaxf(mx, __shfl_xor_sync(0xFFFFFFFFu, mx, o));
        if (lane == 0) atomicMax(&g_FN, __float_as_uint(mx));
    }
}

__global__ void k_refinit()
{
    float inv = 1.0f/__uint_as_float(g_FN);
    int c = blockIdx.x;     // 128
    int u = threadIdx.x;    // 256
    #pragma unroll 4
    for (int ch = 0; ch < 64; ++ch)
        g_RA[ch*RCHN + (c+4)*RSTR + 4 + u] = g_HFT[(ch & 31)*32768 + c*256 + u] * inv;
}

// ---------------- FUSED refine conv: tt+rr, 2 c-rows/thread, cp.async dbuf weights ----------------
__global__ __launch_bounds__(256) void k_refconv(
    const float* __restrict__ Wt, const float* __restrict__ Wr,
    const float* __restrict__ Bt, const float* __restrict__ Br,
    int swap)
{
    const float* RIN  = swap ? g_RB : g_RA;
    float*       ROUT = swap ? g_RA : g_RB;
    int cpair = blockIdx.x >> 2;   // 0..63
    int osel  = blockIdx.x & 3;
    int o0    = osel * 8;
    int c0    = cpair * 2;
    int u     = threadIdx.x;       // 256
    int tidx  = threadIdx.x;
    extern __shared__ float4 swb[];    // 2 x 2304 float4 = 72KB
    uint32_t sa0 = smem_u32(swb);
    uint32_t sa1 = smem_u32(swb + 2304);

    auto prefetch = [&](int kh, uint32_t sa){
        for (int i = tidx; i < 2304; i += 256) {
            int kwci = i >> 2, part = i & 3;
            int koff = (kh*9 + (kwci >> 6))*2048 + (kwci & 63)*32 + o0;
            const float* src = (part < 2) ? (Wt + koff + part*4)
                                          : (Wr + koff + (part-2)*4);
            cpasync16(sa + (uint32_t)i*16u, src);
        }
        CP_COMMIT();
    };

    uint64_t accT0[4] = {0,0,0,0}, accR0[4] = {0,0,0,0};
    uint64_t accT1[4] = {0,0,0,0}, accR1[4] = {0,0,0,0};

    prefetch(0, sa0);

    for (int kh = 0; kh < 9; ++kh) {
        const float4* cur = (kh & 1) ? (swb + 2304) : swb;
        CP_WAIT0();
        __syncthreads();
        if (kh + 1 < 9) prefetch(kh + 1, (kh & 1) ? sa0 : sa1);

        const float* xr0 = RIN + (c0+kh)*RSTR + u;
        const float* xr1 = xr0 + RSTR;
        for (int kw = 0; kw < 9; ++kw) {
            const ulonglong2* wp = (const ulonglong2*)(cur + kw*256);
            #pragma unroll 1
            for (int cg = 0; cg < 16; ++cg) {
                float xs0[4], xs1[4];
                #pragma unroll
                for (int j = 0; j < 4; ++j) {
                    xs0[j] = __ldg(xr0 + kw + (cg*4+j)*RCHN);
                    xs1[j] = __ldg(xr1 + kw + (cg*4+j)*RCHN);
                }
                #pragma unroll
                for (int j = 0; j < 4; ++j) {
                    int ci = cg*4 + j;
                    uint64_t x0 = pack2(xs0[j]);
                    uint64_t x1 = pack2(xs1[j]);
                    ulonglong2 t01 = wp[4*ci];
                    ulonglong2 t23 = wp[4*ci+1];
                    ulonglong2 r01 = wp[4*ci+2];
                    ulonglong2 r23 = wp[4*ci+3];
                    fma2(accT0[0], x0, t01.x); fma2(accT0[1], x0, t01.y);
                    fma2(accT0[2], x0, t23.x); fma2(accT0[3], x0, t23.y);
                    fma2(accR0[0], x0, r01.x); fma2(accR0[1], x0, r01.y);
                    fma2(accR0[2], x0, r23.x); fma2(accR0[3], x0, r23.y);
                    fma2(accT1[0], x1, t01.x); fma2(accT1[1], x1, t01.y);
                    fma2(accT1[2], x1, t23.x); fma2(accT1[3], x1, t23.y);
                    fma2(accR1[0], x1, r01.x); fma2(accR1[1], x1, r01.y);
                    fma2(accR1[2], x1, r23.x); fma2(accR1[3], x1, r23.y);
                }
            }
        }
    }
    // epilogue row 0
    {
        int e = (c0+4)*RSTR + 4 + u;
        #pragma unroll
        for (int p = 0; p < 4; ++p) {
            float2 vt = unpack2(accT0[p]);
            float2 vr = unpack2(accR0[p]);
            float tv[2] = {vt.x, vt.y};
            float rv[2] = {vr.x, vr.y};
            #pragma unroll
            for (int s = 0; s < 2; ++s) {
                int k = o0 + 2*p + s;
                float t = dfh_tanh(tv[s] + __ldg(Bt + k));
                float rraw = rv[s] + __ldg(Br + k);
                float rr = (rraw > 0.0f ? rraw : 0.0f)*0.98f + 0.02f*rraw;
                ROUT[k*RCHN + e]      = t  + RIN[k*RCHN + e];
                ROUT[(32+k)*RCHN + e] = rr + RIN[(32+k)*RCHN + e];
            }
        }
    }
    // epilogue row 1
    {
        int e = (c0+5)*RSTR + 4 + u;
        #pragma unroll
        for (int p = 0; p < 4; ++p) {
            float2 vt = unpack2(accT1[p]);
            float2 vr = unpack2(accR1[p]);
            float tv[2] = {vt.x, vt.y};
            float rv[2] = {vr.x, vr.y};
            #pragma unroll
            for (int s = 0; s < 2; ++s) {
                int k = o0 + 2*p + s;
                float t = dfh_tanh(tv[s] + __ldg(Bt + k));
                float rraw = rv[s] + __ldg(Br + k);
                float rr = (rraw > 0.0f ? rraw : 0.0f)*0.98f + 0.02f*rraw;
                ROUT[k*RCHN + e]      = t  + RIN[k*RCHN + e];
                ROUT[(32+k)*RCHN + e] = rr + RIN[(32+k)*RCHN + e];
            }
        }
    }
}

// ---------------- final dense (96 -> 2) ----------------
__global__ void k_final(const float* __restrict__ dw, const float* __restrict__ db,
                        float* __restrict__ out)
{
    int c = blockIdx.x;     // 128
    int u = threadIdx.x;    // 256
    int rpos = (c+4)*RSTR + 4 + u;
    int hpos = c*256 + u;
    float fn = __uint_as_float(g_FN);
    float a0 = __ldg(db), a1 = __ldg(db+1);
    #pragma unroll 8
    for (int p = 0; p < 64; ++p) {
        float v = g_RA[p*RCHN + rpos] * fn;
        a0 += v*__ldg(dw + 2*p);
        a1 += v*__ldg(dw + 2*p + 1);
    }
    #pragma unroll 8
    for (int q = 0; q < 32; ++q) {
        float v = g_HFT[q*32768 + hpos];
        a0 += v*__ldg(dw + 2*(64+q));
        a1 += v*__ldg(dw + 2*(64+q) + 1);
    }
    out[hpos*2]     = a0;
    out[hpos*2 + 1] = a1/fn;
}

// ---------------- launch ----------------
extern "C" void kernel_launch(void* const* d_in, const int* in_sizes, int n_in,
                              void* d_out, int out_size)
{
    const float* times    = (const float*)d_in[0];
    const float* times_in = (const float*)d_in[1];
    const float* inp_nc   = (const float*)d_in[2];
    const float* inp_c    = (const float*)d_in[3];
    const float* cdw  = (const float*)d_in[4];
    const float* cdb  = (const float*)d_in[5];
    const float* cwy1 = (const float*)d_in[6];
    const float* cby1 = (const float*)d_in[7];
    const float* cwy2 = (const float*)d_in[8];
    const float* cby2 = (const float*)d_in[9];
    const float* cwz0 = (const float*)d_in[10];
    const float* cbz0 = (const float*)d_in[11];
    const float* hdw  = (const float*)d_in[12];
    const float* hdb  = (const float*)d_in[13];
    const float* hwy1 = (const float*)d_in[14];
    const float* hby1 = (const float*)d_in[15];
    const float* hwy2 = (const float*)d_in[16];
    const float* hby2 = (const float*)d_in[17];
    const float* hwz0 = (const float*)d_in[18];
    const float* hbz0 = (const float*)d_in[19];
    const float* rwr  = (const float*)d_in[20];
    const float* rbr  = (const float*)d_in[21];
    const float* rwt  = (const float*)d_in[22];
    const float* rbt  = (const float*)d_in[23];
    const float* dw   = (const float*)d_in[24];
    const float* db   = (const float*)d_in[25];
    float* out = (float*)d_out;

    // dynamic smem opt-in (idempotent; capture-safe)
    cudaFuncSetAttribute(k_wave_all<256,128,160,136>,
                         cudaFuncAttributeMaxDynamicSharedMemorySize, 61440);
    cudaFuncSetAttribute(k_wave_all<128,256,288,264>,
                         cudaFuncAttributeMaxDynamicSharedMemorySize, 61440);
    cudaFuncSetAttribute(k_refconv,
                         cudaFuncAttributeMaxDynamicSharedMemorySize, 73728);

    // ---- fidnet 1: H=256, W=128, XS=160, GS=136 ----
    k_zero3<<<512,256>>>();           // also resets g_barcnt
    k_dense1<<<256,128>>>(inp_nc, inp_c, times, times_in, cdw, cdb);
    k_wave_all<256,128,160,136><<<128,256,61440>>>(cwy1, cby1, cwy2, cby2, cwz0, cbz0);

    // ---- spectral glue ----
    k_c1<<<dim3(256,16),128>>>();
    k_c2<<<dim3(128,16),128>>>(times);

    // ---- fidnet 2: H=128, W=256, XS=288, GS=264 ----
    k_zero3<<<512,256>>>();           // resets g_barcnt again
    k_dense2<<<128,256>>>(hdw, hdb);
    k_wave_all<128,256,288,264><<<128,256,61440>>>(hwy1, hby1, hwy2, hby2, hwz0, hbz0);

    // ---- hout_ft ----
    k_stageD<<<dim3(128,32),256>>>();

    // ---- fnorm + refine ----
    k_fninit<<<1,1>>>();
    k_fnred<<<256,256>>>();
    k_zeroref<<<512,256>>>();
    k_refinit<<<128,256>>>();
    for (int i = 0; i < 4; ++i) {
        k_refconv<<<256,256,73728>>>(rwt + i*165888, rwr + i*165888,
                                     rbt + i*32, rbr + i*32, i & 1);
    }

    // ---- final dense + output ----
    k_final<<<128,256>>>(dw, db, out);
}

// round 17
// speedup vs baseline: 1.0765x; 1.0765x over previous
#include <cuda_runtime.h>
#include <math.h>
#include <stdint.h>

// ---------------- constants ----------------
#define NCc 128
#define NTc 256
#define RSTR 264          // refine padded row stride (4 col guards each side)
#define RCHN 35904        // 136*264 floats per refine channel (4 row guards each side)

__device__ __constant__ int c_DILS[15] = {1,2,3,4,6,8,10,12,14,16,18,20,24,28,32};

// ---------------- scratch ----------------
__device__ float g_X[655360];     // activations [H][16][XS] (padded)
__device__ float g_X0[655360];    // dense-layer output snapshot (SKIP = X - X0)
__device__ float g_G[278528];     // gated intermediate [H][8][GS] (padded)
__device__ float g_R2[524288];    // [f(16)][m(128)][t(256)]
__device__ float g_HINP[524288];  // [c(128)][f(16)][t(256)]
__device__ float g_HFT[1048576];  // [g(32)][c(128)][u(256)]
__device__ float g_RA[2297856];   // refine ping [ch(64)][row(136)][RSTR]
__device__ float g_RB[2297856];   // refine pong
__device__ unsigned g_FN;
__device__ unsigned g_barcnt;

__device__ __forceinline__ float dfh_tanh(float x){ return tanhf(x)*0.98f + 0.02f*x; }
__device__ __forceinline__ float dfh_sig (float x){ return 0.98f/(1.0f+expf(-x)) + 0.02f*x; }

// ---------------- packed f32x2 helpers ----------------
__device__ __forceinline__ void fma2(uint64_t &d, uint64_t a, uint64_t b){
    asm("fma.rn.f32x2 %0, %1, %2, %0;" : "+l"(d) : "l"(a), "l"(b));
}
__device__ __forceinline__ uint64_t pack2(float x){
    uint64_t r; asm("mov.b64 %0, {%1, %1};" : "=l"(r) : "f"(x)); return r;
}
__device__ __forceinline__ float2 unpack2(uint64_t v){
    float2 f; asm("mov.b64 {%0, %1}, %2;" : "=f"(f.x), "=f"(f.y) : "l"(v)); return f;
}

// ---------------- cp.async helpers ----------------
__device__ __forceinline__ uint32_t smem_u32(const void* p){
    uint32_t a;
    asm("{ .reg .u64 t; cvta.to.shared.u64 t, %1; cvt.u32.u64 %0, t; }" : "=r"(a) : "l"(p));
    return a;
}
__device__ __forceinline__ void cpasync16(uint32_t dst, const void* src){
    asm volatile("cp.async.cg.shared.global [%0], [%1], 16;" :: "r"(dst), "l"(src));
}
#define CP_COMMIT() asm volatile("cp.async.commit_group;")
#define CP_WAIT0()  asm volatile("cp.async.wait_group 0;")

// ---------------- grid barrier ----------------
__device__ __forceinline__ void gridbar(unsigned &target)
{
    __syncthreads();
    target += gridDim.x;
    if (threadIdx.x == 0) {
        __threadfence();
        atomicAdd(&g_barcnt, 1u);
        while (*((volatile unsigned*)&g_barcnt) < target) { }
        __threadfence();
    }
    __syncthreads();
}

// ---------------- zero helpers ----------------
__global__ void k_zero3()
{
    if (blockIdx.x == 0 && threadIdx.x == 0) g_barcnt = 0u;
    int stride = gridDim.x*blockDim.x;
    for (int i = blockIdx.x*blockDim.x + threadIdx.x; i < 655360; i += stride) {
        g_X[i] = 0.0f;
        if (i < 278528) g_G[i] = 0.0f;
    }
}
__global__ void k_zeroref()
{
    int stride = gridDim.x*blockDim.x;
    for (int i = blockIdx.x*blockDim.x + threadIdx.x; i < 2297856; i += stride) {
        g_RA[i] = 0.0f; g_RB[i] = 0.0f;
    }
}

// ---------------- input dense (4->16); also snapshots X0 ----------------
__global__ void k_dense1(const float* __restrict__ inc, const float* __restrict__ icc,
                         const float* __restrict__ times, const float* __restrict__ tin,
                         const float* __restrict__ cw, const float* __restrict__ cb)
{
    int t = blockIdx.x, c = threadIdx.x;  // 256 x 128
    float i0 = inc[c*NTc + t];
    float i1 = icc[c*NTc + t];
    float i2 = times[t];
    float i3 = tin[c];
    #pragma unroll
    for (int o = 0; o < 16; ++o) {
        float v = i0*cw[o] + i1*cw[16+o] + i2*cw[32+o] + i3*cw[48+o] + cb[o];
        float a = dfh_tanh(v);
        g_X[(t*16+o)*160 + c]  = a;
        g_X0[(t*16+o)*160 + c] = a;
    }
}

// ---------------- PERSISTENT wave stack: cp.async double-buffered weights ----------------
template<int H, int W, int XS, int GS>
__global__ __launch_bounds__(256,1) void k_wave_all(
    const float* __restrict__ wy1a, const float* __restrict__ by1a,
    const float* __restrict__ wy2a, const float* __restrict__ by2a,
    const float* __restrict__ wza,  const float* __restrict__ bza)
{
    constexpr int CHUNKS = W >> 5;
    constexpr int RPB    = 8 / CHUNKS;
    extern __shared__ float4 sDyn[];
    float4* sC = sDyn;            // conv12 buffer (2560 float4)
    float4* sZ = sDyn + 2560;     // convz buffer (1280 float4)
    uint32_t sCa = smem_u32(sC);
    uint32_t sZa = smem_u32(sZ);
    int tidx = threadIdx.x;
    int lane = tidx & 31, warp = tidx >> 5;
    int r = warp / CHUNKS, q = warp - r*CHUNKS;
    int w = (q << 5) + lane;
    int h = blockIdx.x * RPB + r;
    unsigned target = 0;

    // preload layer-0 conv12 weights
    {
        const float4* s1 = (const float4*)wy1a;
        const float4* s2 = (const float4*)wy2a;
        for (int i = tidx; i < 1280; i += 256) {
            cpasync16(sCa + i*16, s1 + i);
            cpasync16(sCa + (1280+i)*16, s2 + i);
        }
        CP_COMMIT(); CP_WAIT0();
    }
    __syncthreads();

    for (int layer = 0; layer < 45; ++layer) {
        int dil = c_DILS[layer % 15];

        // prefetch this layer's convz weights into sZ
        {
            const float4* sz = (const float4*)(wza + layer*5120);
            for (int i = tidx; i < 1280; i += 256)
                cpasync16(sZa + i*16, sz + i);
            CP_COMMIT();
        }

        // ======== phase 1: gated conv pair (16ch -> 8+8 outs) from sC ========
        {
            const float* b1 = by1a + layer*8;
            const float* b2 = by2a + layer*8;

            uint64_t a1[4] = {0,0,0,0};
            uint64_t a2[4] = {0,0,0,0};

            for (int kh = 0; kh < 5; ++kh) {
                int hh = h + kh - 2;
                if ((unsigned)hh >= (unsigned)H) continue;
                const float* xrow = g_X + hh*16*XS;
                for (int kw = 0; kw < 8; ++kw) {
                    int cb0 = (q << 5) + kw*dil;
                    if (cb0 >= W) break;               // warp-uniform
                    const float* xp = xrow + cb0 + lane;
                    const ulonglong2* wp1 = (const ulonglong2*)(sC + (kh*8+kw)*32);
                    const ulonglong2* wp2 = (const ulonglong2*)(sC + 1280 + (kh*8+kw)*32);
                    float xs[16];
                    #pragma unroll
                    for (int ci = 0; ci < 16; ++ci) xs[ci] = xp[ci*XS];
                    #pragma unroll
                    for (int ci = 0; ci < 16; ++ci) {
                        uint64_t xv = pack2(xs[ci]);
                        ulonglong2 wA = wp1[2*ci], wB = wp1[2*ci+1];
                        ulonglong2 wC = wp2[2*ci], wD = wp2[2*ci+1];
                        fma2(a1[0], xv, wA.x); fma2(a1[1], xv, wA.y);
                        fma2(a1[2], xv, wB.x); fma2(a1[3], xv, wB.y);
                        fma2(a2[0], xv, wC.x); fma2(a2[1], xv, wC.y);
                        fma2(a2[2], xv, wD.x); fma2(a2[3], xv, wD.y);
                    }
                }
            }
            #pragma unroll
            for (int p = 0; p < 4; ++p) {
                float2 v1 = unpack2(a1[p]);
                float2 v2 = unpack2(a2[p]);
                int o0 = 2*p;
                float g0 = dfh_tanh(v1.x + __ldg(b1+o0))   * dfh_sig(v2.x + __ldg(b2+o0));
                float g1 = dfh_tanh(v1.y + __ldg(b1+o0+1)) * dfh_sig(v2.y + __ldg(b2+o0+1));
                g_G[(h*8+o0)*GS + w]   = g0;
                g_G[(h*8+o0+1)*GS + w] = g1;
            }
        }
        gridbar(target);
        CP_WAIT0();
        __syncthreads();

        // prefetch NEXT layer's conv12 weights into sC
        if (layer + 1 < 45) {
            const float4* s1 = (const float4*)(wy1a + (layer+1)*5120);
            const float4* s2 = (const float4*)(wy2a + (layer+1)*5120);
            for (int i = tidx; i < 1280; i += 256) {
                cpasync16(sCa + i*16, s1 + i);
                cpasync16(sCa + (1280+i)*16, s2 + i);
            }
            CP_COMMIT();
        }

        // ======== phase 2: z conv (8ch -> all 16 outs) from sZ; X-only update ========
        {
            const float* bz = bza + layer*16;
            uint64_t az[8] = {0,0,0,0,0,0,0,0};

            for (int kh = 0; kh < 5; ++kh) {
                int hh = h + kh - 2;
                if ((unsigned)hh >= (unsigned)H) continue;
                const float* grow = g_G + hh*8*GS + w;
                #pragma unroll
                for (int kw = 0; kw < 8; ++kw) {
                    const float* xp = grow + kw;
                    const ulonglong2* wp = (const ulonglong2*)(sZ + (kh*8+kw)*32);
                    float xs[8];
                    #pragma unroll
                    for (int ci = 0; ci < 8; ++ci) xs[ci] = xp[ci*GS];
                    #pragma unroll
                    for (int ci = 0; ci < 8; ++ci) {
                        uint64_t xv = pack2(xs[ci]);
                        ulonglong2 wA = wp[4*ci],   wB = wp[4*ci+1];
                        ulonglong2 wC = wp[4*ci+2], wD = wp[4*ci+3];
                        fma2(az[0], xv, wA.x); fma2(az[1], xv, wA.y);
                        fma2(az[2], xv, wB.x); fma2(az[3], xv, wB.y);
                        fma2(az[4], xv, wC.x); fma2(az[5], xv, wC.y);
                        fma2(az[6], xv, wD.x); fma2(az[7], xv, wD.y);
                    }
                }
            }
            #pragma unroll
            for (int p = 0; p < 8; ++p) {
                float2 v = unpack2(az[p]);
                int oo = 2*p;
                float z0 = v.x + __ldg(bz+oo);
                float z1 = v.y + __ldg(bz+oo+1);
                int idx0 = (h*16+oo)*XS + w;
                int idx1 = idx0 + XS;
                g_X[idx0] += z0;        // SKIP tracked implicitly as X - X0
                g_X[idx1] += z1;
            }
        }
        gridbar(target);
        CP_WAIT0();
        __syncthreads();
    }
}

// ---------------- stage C1: 4 t per block, twiddle amortized; SKIP = X - X0 ----------------
__global__ void k_c1()
{
    int f  = blockIdx.y;            // 16
    int t0 = blockIdx.x << 2;       // 64 blocks x 4 t
    __shared__ float vr[4][64], vi[4][64], tc[128], ts[128];
    int tid = threadIdx.x;          // 128
    {
        float sv, cv; sincospif((float)tid * (1.0f/64.0f), &sv, &cv);
        tc[tid] = cv; ts[tid] = sv;
    }
    for (int i = tid; i < 256; i += 128) {
        int tt = i >> 6, k = i & 63;
        int base = ((t0+tt)*16+f)*160;
        float cr = g_X[base + 2*k]   - g_X0[base + 2*k];
        float ci = g_X[base + 2*k+1] - g_X0[base + 2*k+1];
        cr = dfh_tanh(cr); ci = dfh_tanh(ci);
        float s = ((k==0)?0.5f:1.0f) * ((k&1)?-1.0f:1.0f);
        vr[tt][k] = s*cr; vi[tt][k] = s*ci;
    }
    __syncthreads();
    int m = tid;
    float acc0 = 0.0f, acc1 = 0.0f, acc2 = 0.0f, acc3 = 0.0f;
    #pragma unroll 8
    for (int k = 0; k < 64; ++k) {
        int j = (k*m) & 127;
        float c = tc[j], s = ts[j];
        acc0 += vr[0][k]*c + vi[0][k]*s;
        acc1 += vr[1][k]*c + vi[1][k]*s;
        acc2 += vr[2][k]*c + vi[2][k]*s;
        acc3 += vr[3][k]*c + vi[3][k]*s;
    }
    g_R2[(f*128+m)*NTc + t0]     = acc0;
    g_R2[(f*128+m)*NTc + t0 + 1] = acc1;
    g_R2[(f*128+m)*NTc + t0 + 2] = acc2;
    g_R2[(f*128+m)*NTc + t0 + 3] = acc3;
}

// ---------------- stage C2 ----------------
__global__ void k_c2(const float* __restrict__ times)
{
    int m = blockIdx.x, f = blockIdx.y;     // 128 x 16
    __shared__ float v[256], tc[256], ts[256];
    int tid = threadIdx.x;                  // 128
    v[tid]       = g_R2[(f*128+m)*NTc + tid];
    v[tid+128]   = g_R2[(f*128+m)*NTc + tid + 128];
    {
        float sv, cv;
        sincospif((float)tid * (1.0f/128.0f), &sv, &cv);        tc[tid] = cv;      ts[tid] = sv;
        sincospif((float)(tid+128) * (1.0f/128.0f), &sv, &cv);  tc[tid+128] = cv;  ts[tid+128] = sv;
    }
    __syncthreads();
    int k = tid;
    float zm = (k==0) ? 1.0f : ((fabsf(times[2*k]) > 0.0f) ? 1.0f : 0.0f);
    float scale = zm * ((k&1)?-1.0f:1.0f) * (1.0f/128.0f);
    float ar = 0.0f, ai = 0.0f;
    #pragma unroll 8
    for (int t = 0; t < 256; ++t) {
        int j = (t*k) & 255;
        ar += v[t]*tc[j];
        ai += v[t]*ts[j];
    }
    g_HINP[(m*16+f)*NTc + 2*k]   = scale*ar;
    g_HINP[(m*16+f)*NTc + 2*k+1] = scale*ai;
}

// ---------------- dense2 (16->16); also snapshots X0 ----------------
__global__ void k_dense2(const float* __restrict__ hw, const float* __restrict__ hb)
{
    int c = blockIdx.x;       // 128
    int t = threadIdx.x;      // 256
    float in[16];
    #pragma unroll
    for (int f = 0; f < 16; ++f) in[f] = g_HINP[(c*16+f)*NTc + t];
    #pragma unroll
    for (int o = 0; o < 16; ++o) {
        float acc = hb[o];
        #pragma unroll
        for (int f = 0; f < 16; ++f) acc += in[f]*hw[f*16+o];
        float a = dfh_tanh(acc);
        g_X[(c*16+o)*288 + t]  = a;
        g_X0[(c*16+o)*288 + t] = a;
    }
}

// ---------------- stage D (SKIP = X - X0) ----------------
__global__ void k_stageD()
{
    int c = blockIdx.x, g = blockIdx.y;     // 128 x 32
    __shared__ float hr[128], hi[128], tc[256], ts[256];
    int tid = threadIdx.x;                  // 256
    if (tid < 128) {
        int j = tid;
        float v0, v1;
        if (g < 16) {
            int base = (c*16+g)*288;
            float a = g_X[base + 2*j]   - g_X0[base + 2*j];   v0 = dfh_tanh(a);
            float b = g_X[base + 2*j+1] - g_X0[base + 2*j+1]; v1 = dfh_tanh(b);
        } else {
            v0 = g_HINP[(c*16+(g-16))*NTc + 2*j];
            v1 = g_HINP[(c*16+(g-16))*NTc + 2*j+1];
        }
        float s = ((j==0)?0.5f:1.0f) * ((j&1)?-1.0f:1.0f);
        hr[j] = s*v0; hi[j] = s*v1;
    }
    {
        float sv, cv; sincospif((float)tid * (1.0f/128.0f), &sv, &cv);
        tc[tid] = cv; ts[tid] = sv;
    }
    __syncthreads();
    int u = tid;
    float acc = 0.0f;
    #pragma unroll 8
    for (int j = 0; j < 128; ++j) {
        int idx = (j*u) & 255;
        acc += hr[j]*tc[idx] + hi[j]*ts[idx];
    }
    g_HFT[(g*128+c)*NTc + u] = acc;
}

// ---------------- fnorm ----------------
__global__ void k_fninit(){ g_FN = 0u; }

__global__ void k_fnred()
{
    int stride = gridDim.x*blockDim.x;
    float mx = 0.0f;
    for (int i = blockIdx.x*blockDim.x + threadIdx.x; i < 1048576; i += stride)
        mx = fmaxf(mx, fabsf(g_HFT[i]));
    #pragma unroll
    for (int o = 16; o; o >>= 1) mx = fmaxf(mx, __shfl_xor_sync(0xFFFFFFFFu, mx, o));
    __shared__ float sm[8];
    int lane = threadIdx.x & 31, warp = threadIdx.x >> 5;
    if (lane == 0) sm[warp] = mx;
    __syncthreads();
    if (warp == 0) {
        mx = (lane < 8) ? sm[lane] : 0.0f;
        #pragma unroll
        for (int o = 4; o; o >>= 1) mx = fmaxf(mx, __shfl_xor_sync(0xFFFFFFFFu, mx, o));
        if (lane == 0) atomicMax(&g_FN, __float_as_uint(mx));
    }
}

__global__ void k_refinit()
{
    float inv = 1.0f/__uint_as_float(g_FN);
    int c = blockIdx.x;     // 128
    int u = threadIdx.x;    // 256
    #pragma unroll 4
    for (int ch = 0; ch < 64; ++ch)
        g_RA[ch*RCHN + (c+4)*RSTR + 4 + u] = g_HFT[(ch & 31)*32768 + c*256 + u] * inv;
}

// ---------------- FUSED refine conv: tt+rr, 2 c-rows/thread, cp.async dbuf weights ----------------
__global__ __launch_bounds__(256) void k_refconv(
    const float* __restrict__ Wt, const float* __restrict__ Wr,
    const float* __restrict__ Bt, const float* __restrict__ Br,
    int swap)
{
    const float* RIN  = swap ? g_RB : g_RA;
    float*       ROUT = swap ? g_RA : g_RB;
    int cpair = blockIdx.x >> 2;   // 0..63
    int osel  = blockIdx.x & 3;
    int o0    = osel * 8;
    int c0    = cpair * 2;
    int u     = threadIdx.x;       // 256
    int tidx  = threadIdx.x;
    extern __shared__ float4 swb[];    // 2 x 2304 float4 = 72KB
    uint32_t sa0 = smem_u32(swb);
    uint32_t sa1 = smem_u32(swb + 2304);

    auto prefetch = [&](int kh, uint32_t sa){
        for (int i = tidx; i < 2304; i += 256) {
            int kwci = i >> 2, part = i & 3;
            int koff = (kh*9 + (kwci >> 6))*2048 + (kwci & 63)*32 + o0;
            const float* src = (part < 2) ? (Wt + koff + part*4)
                                          : (Wr + koff + (part-2)*4);
            cpasync16(sa + (uint32_t)i*16u, src);
        }
        CP_COMMIT();
    };

    uint64_t accT0[4] = {0,0,0,0}, accR0[4] = {0,0,0,0};
    uint64_t accT1[4] = {0,0,0,0}, accR1[4] = {0,0,0,0};

    prefetch(0, sa0);

    for (int kh = 0; kh < 9; ++kh) {
        const float4* cur = (kh & 1) ? (swb + 2304) : swb;
        CP_WAIT0();
        __syncthreads();
        if (kh + 1 < 9) prefetch(kh + 1, (kh & 1) ? sa0 : sa1);

        const float* xr0 = RIN + (c0+kh)*RSTR + u;
        const float* xr1 = xr0 + RSTR;
        for (int kw = 0; kw < 9; ++kw) {
            const ulonglong2* wp = (const ulonglong2*)(cur + kw*256);
            #pragma unroll 1
            for (int cg = 0; cg < 16; ++cg) {
                float xs0[4], xs1[4];
                #pragma unroll
                for (int j = 0; j < 4; ++j) {
                    xs0[j] = __ldg(xr0 + kw + (cg*4+j)*RCHN);
                    xs1[j] = __ldg(xr1 + kw + (cg*4+j)*RCHN);
                }
                #pragma unroll
                for (int j = 0; j < 4; ++j) {
                    int ci = cg*4 + j;
                    uint64_t x0 = pack2(xs0[j]);
                    uint64_t x1 = pack2(xs1[j]);
                    ulonglong2 t01 = wp[4*ci];
                    ulonglong2 t23 = wp[4*ci+1];
                    ulonglong2 r01 = wp[4*ci+2];
                    ulonglong2 r23 = wp[4*ci+3];
                    fma2(accT0[0], x0, t01.x); fma2(accT0[1], x0, t01.y);
                    fma2(accT0[2], x0, t23.x); fma2(accT0[3], x0, t23.y);
                    fma2(accR0[0], x0, r01.x); fma2(accR0[1], x0, r01.y);
                    fma2(accR0[2], x0, r23.x); fma2(accR0[3], x0, r23.y);
                    fma2(accT1[0], x1, t01.x); fma2(accT1[1], x1, t01.y);
                    fma2(accT1[2], x1, t23.x); fma2(accT1[3], x1, t23.y);
                    fma2(accR1[0], x1, r01.x); fma2(accR1[1], x1, r01.y);
                    fma2(accR1[2], x1, r23.x); fma2(accR1[3], x1, r23.y);
                }
            }
        }
    }
    // epilogue row 0
    {
        int e = (c0+4)*RSTR + 4 + u;
        #pragma unroll
        for (int p = 0; p < 4; ++p) {
            float2 vt = unpack2(accT0[p]);
            float2 vr = unpack2(accR0[p]);
            float tv[2] = {vt.x, vt.y};
            float rv[2] = {vr.x, vr.y};
            #pragma unroll
            for (int s = 0; s < 2; ++s) {
                int k = o0 + 2*p + s;
                float t = dfh_tanh(tv[s] + __ldg(Bt + k));
                float rraw = rv[s] + __ldg(Br + k);
                float rr = (rraw > 0.0f ? rraw : 0.0f)*0.98f + 0.02f*rraw;
                ROUT[k*RCHN + e]      = t  + RIN[k*RCHN + e];
                ROUT[(32+k)*RCHN + e] = rr + RIN[(32+k)*RCHN + e];
            }
        }
    }
    // epilogue row 1
    {
        int e = (c0+5)*RSTR + 4 + u;
        #pragma unroll
        for (int p = 0; p < 4; ++p) {
            float2 vt = unpack2(accT1[p]);
            float2 vr = unpack2(accR1[p]);
            float tv[2] = {vt.x, vt.y};
            float rv[2] = {vr.x, vr.y};
            #pragma unroll
            for (int s = 0; s < 2; ++s) {
                int k = o0 + 2*p + s;
                float t = dfh_tanh(tv[s] + __ldg(Bt + k));
                float rraw = rv[s] + __ldg(Br + k);
                float rr = (rraw > 0.0f ? rraw : 0.0f)*0.98f + 0.02f*rraw;
                ROUT[k*RCHN + e]      = t  + RIN[k*RCHN + e];
                ROUT[(32+k)*RCHN + e] = rr + RIN[(32+k)*RCHN + e];
            }
        }
    }
}

// ---------------- final dense (96 -> 2) ----------------
__global__ void k_final(const float* __restrict__ dw, const float* __restrict__ db,
                        float* __restrict__ out)
{
    int c = blockIdx.x;     // 128
    int u = threadIdx.x;    // 256
    int rpos = (c+4)*RSTR + 4 + u;
    int hpos = c*256 + u;
    float fn = __uint_as_float(g_FN);
    float a0 = __ldg(db), a1 = __ldg(db+1);
    #pragma unroll 8
    for (int p = 0; p < 64; ++p) {
        float v = g_RA[p*RCHN + rpos] * fn;
        a0 += v*__ldg(dw + 2*p);
        a1 += v*__ldg(dw + 2*p + 1);
    }
    #pragma unroll 8
    for (int q = 0; q < 32; ++q) {
        float v = g_HFT[q*32768 + hpos];
        a0 += v*__ldg(dw + 2*(64+q));
        a1 += v*__ldg(dw + 2*(64+q) + 1);
    }
    out[hpos*2]     = a0;
    out[hpos*2 + 1] = a1/fn;
}

// ---------------- launch ----------------
extern "C" void kernel_launch(void* const* d_in, const int* in_sizes, int n_in,
                              void* d_out, int out_size)
{
    const float* times    = (const float*)d_in[0];
    const float* times_in = (const float*)d_in[1];
    const float* inp_nc   = (const float*)d_in[2];
    const float* inp_c    = (const float*)d_in[3];
    const float* cdw  = (const float*)d_in[4];
    const float* cdb  = (const float*)d_in[5];
    const float* cwy1 = (const float*)d_in[6];
    const float* cby1 = (const float*)d_in[7];
    const float* cwy2 = (const float*)d_in[8];
    const float* cby2 = (const float*)d_in[9];
    const float* cwz0 = (const float*)d_in[10];
    const float* cbz0 = (const float*)d_in[11];
    const float* hdw  = (const float*)d_in[12];
    const float* hdb  = (const float*)d_in[13];
    const float* hwy1 = (const float*)d_in[14];
    const float* hby1 = (const float*)d_in[15];
    const float* hwy2 = (const float*)d_in[16];
    const float* hby2 = (const float*)d_in[17];
    const float* hwz0 = (const float*)d_in[18];
    const float* hbz0 = (const float*)d_in[19];
    const float* rwr  = (const float*)d_in[20];
    const float* rbr  = (const float*)d_in[21];
    const float* rwt  = (const float*)d_in[22];
    const float* rbt  = (const float*)d_in[23];
    const float* dw   = (const float*)d_in[24];
    const float* db   = (const float*)d_in[25];
    float* out = (float*)d_out;

    // dynamic smem opt-in (idempotent; capture-safe)
    cudaFuncSetAttribute(k_wave_all<256,128,160,136>,
                         cudaFuncAttributeMaxDynamicSharedMemorySize, 61440);
    cudaFuncSetAttribute(k_wave_all<128,256,288,264>,
                         cudaFuncAttributeMaxDynamicSharedMemorySize, 61440);
    cudaFuncSetAttribute(k_refconv,
                         cudaFuncAttributeMaxDynamicSharedMemorySize, 73728);

    // ---- fidnet 1: H=256, W=128, XS=160, GS=136 ----
    k_zero3<<<512,256>>>();           // also resets g_barcnt
    k_dense1<<<256,128>>>(inp_nc, inp_c, times, times_in, cdw, cdb);
    k_wave_all<256,128,160,136><<<128,256,61440>>>(cwy1, cby1, cwy2, cby2, cwz0, cbz0);

    // ---- spectral glue ----
    k_c1<<<dim3(64,16),128>>>();
    k_c2<<<dim3(128,16),128>>>(times);

    // ---- fidnet 2: H=128, W=256, XS=288, GS=264 ----
    k_zero3<<<512,256>>>();           // resets g_barcnt again
    k_dense2<<<128,256>>>(hdw, hdb);
    k_wave_all<128,256,288,264><<<128,256,61440>>>(hwy1, hby1, hwy2, hby2, hwz0, hbz0);

    // ---- hout_ft ----
    k_stageD<<<dim3(128,32),256>>>();

    // ---- fnorm + refine ----
    k_fninit<<<1,1>>>();
    k_fnred<<<256,256>>>();
    k_zeroref<<<512,256>>>();
    k_refinit<<<128,256>>>();
    for (int i = 0; i < 4; ++i) {
        k_refconv<<<256,256,73728>>>(rwt + i*165888, rwr + i*165888,
                                     rbt + i*32, rbr + i*32, i & 1);
    }

    // ---- final dense + output ----
    k_final<<<128,256>>>(dw, db, out);
}